// round 6
// baseline (speedup 1.0000x reference)
#include <cuda_runtime.h>
#include <cstdint>

// VersatileConvSE3  E=16384, C=O=32, D=S=16, F=44, M=32
#define E_TOT 16384
#define NE    16
#define NTHR  512
#define NBLK  (E_TOT / NE)

typedef unsigned long long u64;
#define FMA2(d,a,b,c) asm("fma.rn.f32x2 %0, %1, %2, %3;" : "=l"(d) : "l"(a), "l"(b), "l"(c))
#define ADD2(d,a,b)   asm("add.rn.f32x2 %0, %1, %2;"     : "=l"(d) : "l"(a), "l"(b))
__device__ __forceinline__ u64 pk2(float a, float b) {
    u64 r; asm("mov.b64 %0, {%1, %2};" : "=l"(r) : "f"(a), "f"(b)); return r;
}

__device__ float g_H[E_TOT * 32];

__device__ __forceinline__ float warp_sum(float v) {
    v += __shfl_xor_sync(0xffffffffu, v, 16);
    v += __shfl_xor_sync(0xffffffffu, v, 8);
    v += __shfl_xor_sync(0xffffffffu, v, 4);
    v += __shfl_xor_sync(0xffffffffu, v, 2);
    v += __shfl_xor_sync(0xffffffffu, v, 1);
    return v;
}

__global__ __launch_bounds__(256) void mlp_kernel(
    const float* __restrict__ inv,
    const float* __restrict__ w1, const float* __restrict__ b1,
    const float* __restrict__ g1, const float* __restrict__ be1,
    const float* __restrict__ w2, const float* __restrict__ b2,
    const float* __restrict__ g2, const float* __restrict__ be2)
{
    const int e = blockIdx.x * 8 + (threadIdx.x >> 5);
    const int lane = threadIdx.x & 31;
    const float* x = inv + e * 16;
    float y = b1[lane];
    #pragma unroll
    for (int d = 0; d < 16; ++d) y += x[d] * w1[lane * 16 + d];
    float mu  = warp_sum(y) * (1.0f/32.0f);
    float dz  = y - mu;
    float var = warp_sum(dz*dz) * (1.0f/32.0f);
    float h1  = fmaxf(dz * rsqrtf(var + 1e-5f) * g1[lane] + be1[lane], 0.0f);
    float y2 = b2[lane];
    #pragma unroll
    for (int m = 0; m < 32; ++m)
        y2 += __shfl_sync(0xffffffffu, h1, m) * w2[lane * 32 + m];
    mu  = warp_sum(y2) * (1.0f/32.0f);
    dz  = y2 - mu;
    var = warp_sum(dz*dz) * (1.0f/32.0f);
    g_H[e * 32 + lane] = fmaxf(dz * rsqrtf(var + 1e-5f) * g2[lane] + be2[lane], 0.0f);
}

// smem float offsets (all float4-aligned)
#define OF_H    0        // [m32][e16]                  512
#define OF_BAS  512      // [e16][d16][s16]             4096
#define OF_T    4608     // [c32] stride 324, e str 20  10368
#define OF_RW   14976    // [row1024][18]               18432
#define OF_W3   33408    // [lrow512][44]               22528
#define SMEM_FLOATS 55936
#define T_CS 324
#define T_ES 20

__global__ __launch_bounds__(NTHR, 1) void conv_kernel(
    const float* __restrict__ feat,
    const float* __restrict__ basis,
    const float* __restrict__ w3,
    float* __restrict__ out)
{
    extern __shared__ __align__(16) float sm[];
    const int tid = threadIdx.x;
    const int e0  = blockIdx.x * NE;

    // roles
    const int tg_e = tid >> 5, tg_c = tid & 31;          // T-gen
    const int s_r  = tid >> 3, s_k = tid & 7;            // w3 stager
    const int b_og = (tid >> 4) & 15, b_e = tid & 15;    // Phase B
    const int b_cq = tid >> 8;
    const int b_o0 = b_og * 2, b_o1 = b_o0 + 1;

    // stage H transposed [m][e]
    sm[OF_H + (tid & 31) * 16 + (tid >> 5)] = g_H[(size_t)(e0 + (tid >> 5)) * 32 + (tid & 31)];

    // feat -> regs (16 floats for (tg_e, tg_c))
    float fr[16];
    {
        const float4* fp = (const float4*)(feat + ((size_t)(e0 + tg_e) * 32 + tg_c) * 16);
        #pragma unroll
        for (int i = 0; i < 4; ++i) {
            float4 v = __ldg(fp + i);
            fr[4*i] = v.x; fr[4*i+1] = v.y; fr[4*i+2] = v.z; fr[4*i+3] = v.w;
        }
    }

    // basis prefetch (f=0)
    const float* bas_base = basis + (((size_t)(e0 + (tid >> 5)) * 16 + ((tid >> 1) & 15)) * 44) * 16 + (tid & 1) * 8;
    float4 bpre0 = __ldg((const float4*)bas_base);
    float4 bpre1 = __ldg((const float4*)bas_base + 1);

    u64 acc0[8], acc1[8];
    #pragma unroll
    for (int k = 0; k < 8; ++k) { acc0[k] = 0ull; acc1[k] = 0ull; }

    __syncthreads();

    // Phase A helper: one thread = one w3 row (all 16 e, all 32 m)
    #define PHASE_A(GR)                                                          \
    {                                                                            \
        u64 A_[8];                                                               \
        _Pragma("unroll")                                                        \
        for (int k = 0; k < 8; ++k) A_[k] = 0ull;                                \
        const float* wrow = sm + OF_W3 + tid * 44;                               \
        _Pragma("unroll")                                                        \
        for (int mq = 0; mq < 8; ++mq) {                                         \
            float4 w = *(const float4*)(wrow + mq * 4);                          \
            float wv[4] = { w.x, w.y, w.z, w.w };                                \
            _Pragma("unroll")                                                    \
            for (int mm = 0; mm < 4; ++mm) {                                     \
                const int m = mq * 4 + mm;                                       \
                const ulonglong2* hp = (const ulonglong2*)(sm + OF_H + m * 16);  \
                ulonglong2 h01 = hp[0], h23 = hp[1], h45 = hp[2], h67 = hp[3];   \
                u64 p = pk2(wv[mm], wv[mm]);                                     \
                FMA2(A_[0], p, h01.x, A_[0]); FMA2(A_[1], p, h01.y, A_[1]);      \
                FMA2(A_[2], p, h23.x, A_[2]); FMA2(A_[3], p, h23.y, A_[3]);      \
                FMA2(A_[4], p, h45.x, A_[4]); FMA2(A_[5], p, h45.y, A_[5]);      \
                FMA2(A_[6], p, h67.x, A_[6]); FMA2(A_[7], p, h67.y, A_[7]);      \
            }                                                                    \
        }                                                                        \
        u64* dp = (u64*)(sm + OF_RW + (size_t)(GR) * 18);                        \
        _Pragma("unroll")                                                        \
        for (int k = 0; k < 8; ++k) dp[k] = A_[k];                               \
    }

    for (int f = 0; f < 44; ++f) {
        // stage basis slice
        {
            float4* bp = (float4*)(sm + OF_BAS + tid * 8);
            bp[0] = bpre0; bp[1] = bpre1;
        }
        __syncthreads();   // sync1: bas ready; sT/sRW/sW3 of f-1 consumed
        if (f < 43) {
            const float* bs = bas_base + (size_t)(f + 1) * 16;
            bpre0 = __ldg((const float4*)bs);
            bpre1 = __ldg((const float4*)bs + 1);
        }

        // ---- stage w3 half 0 (rows 0..511 = o 0..15), T-gen overlaps LDG ----
        float4 w_[8];
        #pragma unroll
        for (int i = 0; i < 8; ++i) {
            const int lr = i * 64 + s_r;                 // gr == lr for half 0
            const int o = lr >> 5, c = lr & 31;
            w_[i] = __ldg((const float4*)(w3 + ((size_t)o * 1408 + (size_t)c * 44 + f) * 32 + s_k * 4));
        }

        // T-gen: T[c][e][s] = sum_d feat*bas
        {
            u64 t[8];
            #pragma unroll
            for (int k = 0; k < 8; ++k) t[k] = 0ull;
            const char* bb = (const char*)(sm + OF_BAS + tg_e * 256);
            #pragma unroll
            for (int d = 0; d < 16; ++d) {
                u64 fp2 = pk2(fr[d], fr[d]);
                const ulonglong2* bp = (const ulonglong2*)(bb + d * 64);
                ulonglong2 q0 = bp[0], q1 = bp[1], q2 = bp[2], q3 = bp[3];
                FMA2(t[0], fp2, q0.x, t[0]); FMA2(t[1], fp2, q0.y, t[1]);
                FMA2(t[2], fp2, q1.x, t[2]); FMA2(t[3], fp2, q1.y, t[3]);
                FMA2(t[4], fp2, q2.x, t[4]); FMA2(t[5], fp2, q2.y, t[5]);
                FMA2(t[6], fp2, q3.x, t[6]); FMA2(t[7], fp2, q3.y, t[7]);
            }
            ulonglong2* tp = (ulonglong2*)(sm + OF_T + tg_c * T_CS + tg_e * T_ES);
            #pragma unroll
            for (int k = 0; k < 4; ++k) { ulonglong2 v; v.x = t[2*k]; v.y = t[2*k+1]; tp[k] = v; }
        }

        #pragma unroll
        for (int i = 0; i < 8; ++i) {
            const int lr = i * 64 + s_r;
            *(float4*)(sm + OF_W3 + lr * 44 + s_k * 4) = w_[i];
        }
        __syncthreads();   // sync2: sW3 half0 + sT ready

        PHASE_A(tid)       // rw rows 0..511
        __syncthreads();   // sync3: half0 rw done, sW3 free

        // ---- stage w3 half 1 (rows 512..1023 = o 16..31) ----
        #pragma unroll
        for (int i = 0; i < 8; ++i) {
            const int lr = i * 64 + s_r;
            const int gr = 512 + lr;
            const int o = gr >> 5, c = gr & 31;
            w_[i] = __ldg((const float4*)(w3 + ((size_t)o * 1408 + (size_t)c * 44 + f) * 32 + s_k * 4));
        }
        #pragma unroll
        for (int i = 0; i < 8; ++i) {
            const int lr = i * 64 + s_r;
            *(float4*)(sm + OF_W3 + lr * 44 + s_k * 4) = w_[i];
        }
        __syncthreads();   // sync4: sW3 half1 ready

        PHASE_A(512 + tid) // rw rows 512..1023
        __syncthreads();   // sync5: all rw ready

        // ---- Phase B: acc[e][o][s] += rw[o*32+c][e] * T[c][e][s] ----
        {
            const float* rwb = sm + OF_RW;
            const int r0 = b_o0 * 32, r1 = b_o1 * 32;
            #pragma unroll
            for (int ci = 0; ci < 16; ++ci) {
                const int c = b_cq * 16 + ci;
                float rv0 = rwb[(r0 + c) * 18 + b_e];
                float rv1 = rwb[(r1 + c) * 18 + b_e];
                const ulonglong2* tp = (const ulonglong2*)(sm + OF_T + c * T_CS + b_e * T_ES);
                ulonglong2 q0 = tp[0], q1 = tp[1], q2 = tp[2], q3 = tp[3];
                u64 rp0 = pk2(rv0, rv0), rp1 = pk2(rv1, rv1);
                FMA2(acc0[0], rp0, q0.x, acc0[0]); FMA2(acc0[1], rp0, q0.y, acc0[1]);
                FMA2(acc0[2], rp0, q1.x, acc0[2]); FMA2(acc0[3], rp0, q1.y, acc0[3]);
                FMA2(acc0[4], rp0, q2.x, acc0[4]); FMA2(acc0[5], rp0, q2.y, acc0[5]);
                FMA2(acc0[6], rp0, q3.x, acc0[6]); FMA2(acc0[7], rp0, q3.y, acc0[7]);
                FMA2(acc1[0], rp1, q0.x, acc1[0]); FMA2(acc1[1], rp1, q0.y, acc1[1]);
                FMA2(acc1[2], rp1, q1.x, acc1[2]); FMA2(acc1[3], rp1, q1.y, acc1[3]);
                FMA2(acc1[4], rp1, q2.x, acc1[4]); FMA2(acc1[5], rp1, q2.y, acc1[5]);
                FMA2(acc1[6], rp1, q3.x, acc1[6]); FMA2(acc1[7], rp1, q3.y, acc1[7]);
            }
        }
    }

    // reduce the two c-halves and store
    __syncthreads();
    if (tid >= 256) {
        u64* sp = (u64*)(sm + OF_RW) + (size_t)(tid - 256) * 16;
        #pragma unroll
        for (int k = 0; k < 8; ++k) { sp[k] = acc0[k]; sp[8 + k] = acc1[k]; }
    }
    __syncthreads();
    if (tid < 256) {
        const u64* sp = (const u64*)(sm + OF_RW) + (size_t)tid * 16;
        #pragma unroll
        for (int k = 0; k < 8; ++k) {
            ADD2(acc0[k], acc0[k], sp[k]);
            ADD2(acc1[k], acc1[k], sp[8 + k]);
        }
        float* op0 = out + (((size_t)(e0 + b_e) * 32) + b_o0) * 16;
        float* op1 = out + (((size_t)(e0 + b_e) * 32) + b_o1) * 16;
        #pragma unroll
        for (int k = 0; k < 4; ++k) {
            ulonglong2 v;
            v.x = acc0[2*k]; v.y = acc0[2*k+1]; ((ulonglong2*)op0)[k] = v;
            v.x = acc1[2*k]; v.y = acc1[2*k+1]; ((ulonglong2*)op1)[k] = v;
        }
    }
    #undef PHASE_A
}

extern "C" void kernel_launch(void* const* d_in, const int* in_sizes, int n_in,
                              void* d_out, int out_size)
{
    const float* features = (const float*)d_in[0];
    const float* inv      = (const float*)d_in[1];
    const float* basis    = (const float*)d_in[2];
    const float* w1  = (const float*)d_in[3];
    const float* b1  = (const float*)d_in[4];
    const float* g1  = (const float*)d_in[5];
    const float* be1 = (const float*)d_in[6];
    const float* w2  = (const float*)d_in[7];
    const float* b2  = (const float*)d_in[8];
    const float* g2  = (const float*)d_in[9];
    const float* be2 = (const float*)d_in[10];
    const float* w3  = (const float*)d_in[11];
    float* out = (float*)d_out;

    cudaFuncSetAttribute(conv_kernel, cudaFuncAttributeMaxDynamicSharedMemorySize,
                         SMEM_FLOATS * (int)sizeof(float));

    mlp_kernel<<<E_TOT / 8, 256>>>(inv, w1, b1, g1, be1, w2, b2, g2, be2);
    conv_kernel<<<NBLK, NTHR, SMEM_FLOATS * sizeof(float)>>>(features, basis, w3, out);
}

// round 7
// speedup vs baseline: 1.0996x; 1.0996x over previous
#include <cuda_runtime.h>
#include <cstdint>

// VersatileConvSE3  E=16384, C=O=32, D=S=16, F=44, M=32
#define E_TOT 16384
#define NE    16
#define NTHR  512
#define NBLK  (E_TOT / NE)

typedef unsigned long long u64;
#define FMA2(d,a,b,c) asm("fma.rn.f32x2 %0, %1, %2, %3;" : "=l"(d) : "l"(a), "l"(b), "l"(c))
__device__ __forceinline__ u64 pk2(float a, float b) {
    u64 r; asm("mov.b64 %0, {%1, %2};" : "=l"(r) : "f"(a), "f"(b)); return r;
}

__device__ float g_H[E_TOT * 32];

__device__ __forceinline__ float warp_sum(float v) {
    v += __shfl_xor_sync(0xffffffffu, v, 16);
    v += __shfl_xor_sync(0xffffffffu, v, 8);
    v += __shfl_xor_sync(0xffffffffu, v, 4);
    v += __shfl_xor_sync(0xffffffffu, v, 2);
    v += __shfl_xor_sync(0xffffffffu, v, 1);
    return v;
}

__global__ __launch_bounds__(256) void mlp_kernel(
    const float* __restrict__ inv,
    const float* __restrict__ w1, const float* __restrict__ b1,
    const float* __restrict__ g1, const float* __restrict__ be1,
    const float* __restrict__ w2, const float* __restrict__ b2,
    const float* __restrict__ g2, const float* __restrict__ be2)
{
    const int e = blockIdx.x * 8 + (threadIdx.x >> 5);
    const int lane = threadIdx.x & 31;
    const float* x = inv + e * 16;
    float y = b1[lane];
    #pragma unroll
    for (int d = 0; d < 16; ++d) y += x[d] * w1[lane * 16 + d];
    float mu  = warp_sum(y) * (1.0f/32.0f);
    float dz  = y - mu;
    float var = warp_sum(dz*dz) * (1.0f/32.0f);
    float h1  = fmaxf(dz * rsqrtf(var + 1e-5f) * g1[lane] + be1[lane], 0.0f);
    float y2 = b2[lane];
    #pragma unroll
    for (int m = 0; m < 32; ++m)
        y2 += __shfl_sync(0xffffffffu, h1, m) * w2[lane * 32 + m];
    mu  = warp_sum(y2) * (1.0f/32.0f);
    dz  = y2 - mu;
    var = warp_sum(dz*dz) * (1.0f/32.0f);
    g_H[e * 32 + lane] = fmaxf(dz * rsqrtf(var + 1e-5f) * g2[lane] + be2[lane], 0.0f);
}

// smem float offsets (all float4-aligned)
#define OF_H    0        // [m32][e16]                  512
#define OF_BAS  512      // [e16][d16][s16]             4096
#define OF_T    4608     // [c32] stride 324, e str 20  10368
#define OF_RW   14976    // [row1024][18]               18432
#define OF_W3   33408    // [lrow512][36]               18432
#define SMEM_FLOATS 51840   // 207360 bytes
#define T_CS 324
#define T_ES 20

__global__ __launch_bounds__(NTHR, 1) void conv_kernel(
    const float* __restrict__ feat,
    const float* __restrict__ basis,
    const float* __restrict__ w3,
    float* __restrict__ out)
{
    extern __shared__ __align__(16) float sm[];
    const int tid = threadIdx.x;
    const int e0  = blockIdx.x * NE;

    // roles
    const int tg_e = tid >> 5, tg_c = tid & 31;          // T-gen
    const int s_r  = tid >> 3, s_k = tid & 7;            // w3 stager
    const int a_la = tid & 127, a_eq = tid >> 7;         // Phase A: 4 rows x 4 e
    const int b_e  = tid & 15;                           // Phase B
    const int b_og = (tid >> 4) & 15, b_sh = tid >> 8;
    const int b_o0 = b_og * 2, b_o1 = b_o0 + 1;

    // stage H transposed [m][e]
    sm[OF_H + (tid & 31) * 16 + (tid >> 5)] = g_H[(size_t)(e0 + (tid >> 5)) * 32 + (tid & 31)];

    // feat -> regs
    float fr[16];
    {
        const float4* fp = (const float4*)(feat + ((size_t)(e0 + tg_e) * 32 + tg_c) * 16);
        #pragma unroll
        for (int i = 0; i < 4; ++i) {
            float4 v = __ldg(fp + i);
            fr[4*i] = v.x; fr[4*i+1] = v.y; fr[4*i+2] = v.z; fr[4*i+3] = v.w;
        }
    }

    // basis prefetch (f=0)
    const float* bas_base = basis + (((size_t)(e0 + (tid >> 5)) * 16 + ((tid >> 1) & 15)) * 44) * 16 + (tid & 1) * 8;
    float4 bpre0 = __ldg((const float4*)bas_base);
    float4 bpre1 = __ldg((const float4*)bas_base + 1);

    // Phase B persistent accumulators: 2 o x 8 s
    u64 acc0[4], acc1[4];
    #pragma unroll
    for (int k = 0; k < 4; ++k) { acc0[k] = 0ull; acc1[k] = 0ull; }

    __syncthreads();

    // Phase A: 4 rows (la+128i) x 4 e (quad a_eq), 32 m
    #define PHASE_A(HALF)                                                         \
    {                                                                             \
        u64 A_[4][2];                                                             \
        _Pragma("unroll")                                                         \
        for (int i = 0; i < 4; ++i) { A_[i][0] = 0ull; A_[i][1] = 0ull; }         \
        const float* hb = sm + OF_H + a_eq * 4;                                   \
        const float* wb = sm + OF_W3 + a_la * 36;                                 \
        _Pragma("unroll")                                                         \
        for (int mq = 0; mq < 8; ++mq) {                                          \
            float4 w0q = *(const float4*)(wb + mq * 4);                           \
            float4 w1q = *(const float4*)(wb + 128 * 36 + mq * 4);                \
            float4 w2q = *(const float4*)(wb + 256 * 36 + mq * 4);                \
            float4 w3q = *(const float4*)(wb + 384 * 36 + mq * 4);                \
            const float wv0[4] = { w0q.x, w0q.y, w0q.z, w0q.w };                  \
            const float wv1[4] = { w1q.x, w1q.y, w1q.z, w1q.w };                  \
            const float wv2[4] = { w2q.x, w2q.y, w2q.z, w2q.w };                  \
            const float wv3[4] = { w3q.x, w3q.y, w3q.z, w3q.w };                  \
            _Pragma("unroll")                                                     \
            for (int mm = 0; mm < 4; ++mm) {                                      \
                ulonglong2 hv = *(const ulonglong2*)(hb + (mq * 4 + mm) * 16);    \
                u64 p;                                                            \
                p = pk2(wv0[mm], wv0[mm]);                                        \
                FMA2(A_[0][0], p, hv.x, A_[0][0]); FMA2(A_[0][1], p, hv.y, A_[0][1]); \
                p = pk2(wv1[mm], wv1[mm]);                                        \
                FMA2(A_[1][0], p, hv.x, A_[1][0]); FMA2(A_[1][1], p, hv.y, A_[1][1]); \
                p = pk2(wv2[mm], wv2[mm]);                                        \
                FMA2(A_[2][0], p, hv.x, A_[2][0]); FMA2(A_[2][1], p, hv.y, A_[2][1]); \
                p = pk2(wv3[mm], wv3[mm]);                                        \
                FMA2(A_[3][0], p, hv.x, A_[3][0]); FMA2(A_[3][1], p, hv.y, A_[3][1]); \
            }                                                                     \
        }                                                                         \
        _Pragma("unroll")                                                         \
        for (int i = 0; i < 4; ++i) {                                             \
            u64* dp = (u64*)(sm + OF_RW + (size_t)((HALF) * 512 + a_la + 128 * i) * 18 + a_eq * 4); \
            dp[0] = A_[i][0]; dp[1] = A_[i][1];                                   \
        }                                                                         \
    }

    for (int f = 0; f < 44; ++f) {
        // stage basis slice
        {
            float4* bp = (float4*)(sm + OF_BAS + tid * 8);
            bp[0] = bpre0; bp[1] = bpre1;
        }
        __syncthreads();   // sync1
        if (f < 43) {
            const float* bs = bas_base + (size_t)(f + 1) * 16;
            bpre0 = __ldg((const float4*)bs);
            bpre1 = __ldg((const float4*)bs + 1);
        }

        // w3 half-0 LDG (overlapped by T-gen)
        float4 w_[8];
        #pragma unroll
        for (int i = 0; i < 8; ++i) {
            const int lr = i * 64 + s_r;
            const int o = lr >> 5, c = lr & 31;
            w_[i] = __ldg((const float4*)(w3 + ((size_t)o * 1408 + (size_t)c * 44 + f) * 32 + s_k * 4));
        }

        // T-gen: T[c][e][s] = sum_d feat*bas
        {
            u64 t[8];
            #pragma unroll
            for (int k = 0; k < 8; ++k) t[k] = 0ull;
            const char* bb = (const char*)(sm + OF_BAS + tg_e * 256);
            #pragma unroll
            for (int d = 0; d < 16; ++d) {
                u64 fp2 = pk2(fr[d], fr[d]);
                const ulonglong2* bp = (const ulonglong2*)(bb + d * 64);
                ulonglong2 q0 = bp[0], q1 = bp[1], q2 = bp[2], q3 = bp[3];
                FMA2(t[0], fp2, q0.x, t[0]); FMA2(t[1], fp2, q0.y, t[1]);
                FMA2(t[2], fp2, q1.x, t[2]); FMA2(t[3], fp2, q1.y, t[3]);
                FMA2(t[4], fp2, q2.x, t[4]); FMA2(t[5], fp2, q2.y, t[5]);
                FMA2(t[6], fp2, q3.x, t[6]); FMA2(t[7], fp2, q3.y, t[7]);
            }
            ulonglong2* tp = (ulonglong2*)(sm + OF_T + tg_c * T_CS + tg_e * T_ES);
            #pragma unroll
            for (int k = 0; k < 4; ++k) { ulonglong2 v; v.x = t[2*k]; v.y = t[2*k+1]; tp[k] = v; }
        }

        #pragma unroll
        for (int i = 0; i < 8; ++i) {
            const int lr = i * 64 + s_r;
            *(float4*)(sm + OF_W3 + lr * 36 + s_k * 4) = w_[i];
        }
        __syncthreads();   // sync2: sW3 half0 + sT ready

        // early prefetch of half-1 w3 (latency hidden behind PHASE_A half 0)
        float4 wn_[8];
        #pragma unroll
        for (int i = 0; i < 8; ++i) {
            const int gr = 512 + i * 64 + s_r;
            const int o = gr >> 5, c = gr & 31;
            wn_[i] = __ldg((const float4*)(w3 + ((size_t)o * 1408 + (size_t)c * 44 + f) * 32 + s_k * 4));
        }

        PHASE_A(0)
        __syncthreads();   // sync3: half0 rw done, sW3 free

        #pragma unroll
        for (int i = 0; i < 8; ++i) {
            const int lr = i * 64 + s_r;
            *(float4*)(sm + OF_W3 + lr * 36 + s_k * 4) = wn_[i];
        }
        __syncthreads();   // sync4: sW3 half1 ready

        PHASE_A(1)
        __syncthreads();   // sync5: all rw ready

        // Phase B: acc[e][2o][8s] += rw[o*32+c][e] * T[c][e][8s], full c
        {
            const float* rwb = sm + OF_RW + b_e;
            const char* tb = (const char*)(sm + OF_T + b_e * T_ES + b_sh * 8);
            #pragma unroll
            for (int c = 0; c < 32; ++c) {
                float rv0 = rwb[(b_o0 * 32 + c) * 18];
                float rv1 = rwb[(b_o1 * 32 + c) * 18];
                const ulonglong2* tp = (const ulonglong2*)(tb + c * (T_CS * 4));
                ulonglong2 qa = tp[0], qb = tp[1];
                u64 rp0 = pk2(rv0, rv0), rp1 = pk2(rv1, rv1);
                FMA2(acc0[0], rp0, qa.x, acc0[0]); FMA2(acc0[1], rp0, qa.y, acc0[1]);
                FMA2(acc0[2], rp0, qb.x, acc0[2]); FMA2(acc0[3], rp0, qb.y, acc0[3]);
                FMA2(acc1[0], rp1, qa.x, acc1[0]); FMA2(acc1[1], rp1, qa.y, acc1[1]);
                FMA2(acc1[2], rp1, qb.x, acc1[2]); FMA2(acc1[3], rp1, qb.y, acc1[3]);
            }
        }
    }

    // direct store: thread owns (e, o0/o1, 8 s at b_sh*8)
    {
        float* op0 = out + (((size_t)(e0 + b_e) * 32) + b_o0) * 16 + b_sh * 8;
        float* op1 = out + (((size_t)(e0 + b_e) * 32) + b_o1) * 16 + b_sh * 8;
        ulonglong2 v;
        v.x = acc0[0]; v.y = acc0[1]; ((ulonglong2*)op0)[0] = v;
        v.x = acc0[2]; v.y = acc0[3]; ((ulonglong2*)op0)[1] = v;
        v.x = acc1[0]; v.y = acc1[1]; ((ulonglong2*)op1)[0] = v;
        v.x = acc1[2]; v.y = acc1[3]; ((ulonglong2*)op1)[1] = v;
    }
    #undef PHASE_A
}

extern "C" void kernel_launch(void* const* d_in, const int* in_sizes, int n_in,
                              void* d_out, int out_size)
{
    const float* features = (const float*)d_in[0];
    const float* inv      = (const float*)d_in[1];
    const float* basis    = (const float*)d_in[2];
    const float* w1  = (const float*)d_in[3];
    const float* b1  = (const float*)d_in[4];
    const float* g1  = (const float*)d_in[5];
    const float* be1 = (const float*)d_in[6];
    const float* w2  = (const float*)d_in[7];
    const float* b2  = (const float*)d_in[8];
    const float* g2  = (const float*)d_in[9];
    const float* be2 = (const float*)d_in[10];
    const float* w3  = (const float*)d_in[11];
    float* out = (float*)d_out;

    cudaFuncSetAttribute(conv_kernel, cudaFuncAttributeMaxDynamicSharedMemorySize,
                         SMEM_FLOATS * (int)sizeof(float));

    mlp_kernel<<<E_TOT / 8, 256>>>(inv, w1, b1, g1, be1, w2, b2, g2, be2);
    conv_kernel<<<NBLK, NTHR, SMEM_FLOATS * sizeof(float)>>>(features, basis, w3, out);
}